// round 2
// baseline (speedup 1.0000x reference)
#include <cuda_runtime.h>

// Seq2Seq GRU encoder/decoder, persistent per-CTA batch-slice kernel.
// Shapes (fixed): SEQ=256, LABEL=128, B=8192, NF=NO=8, H=64.
#define SEQ_LEN   256
#define LABEL_LEN 128
#define BATCH     8192
#define NF        8
#define NO        8
#define HID       64
#define G3        192   // 3*HID

#define ROWS      64                 // batch rows per CTA
#define NCTA      (BATCH / ROWS)     // 128
#define NTHREADS  256                // 16 (col groups) x 16 (row groups)

struct Smem {
    float whh_t[HID * G3];   // [k][c], c in 0..191 (r|z|n) : Whh transposed
    float wih_t[NF * G3];    // [f][c]
    float wout_t[HID * NO];  // [k][o]
    float brz[2 * HID];      // bih + bhh for r,z gates
    float bin_[HID];         // bih n-gate
    float bhn[HID];          // bhh n-gate
    float bout_s[NO];
    float h_t[HID * ROWS];   // [k][row] : h transposed
    float x_t[NF * ROWS];    // [f][row] : current input transposed
};

__device__ __forceinline__ float sigf(float x) {
    return __fdividef(1.0f, 1.0f + __expf(-x));
}
__device__ __forceinline__ float tanh_(float x) {
    return __fdividef(2.0f, 1.0f + __expf(-2.0f * x)) - 1.0f;
}

__device__ void load_phase_weights(Smem* s, const float* Wih, const float* Whh,
                                   const float* bih, const float* bhh) {
    int tid = threadIdx.x;
    // Whh [192,64] row-major -> whh_t[k*192 + c]
    for (int idx = tid; idx < G3 * HID; idx += NTHREADS) {
        int c = idx / HID, k = idx % HID;
        s->whh_t[k * G3 + c] = Whh[idx];
    }
    // Wih [192,8] -> wih_t[f*192 + c]
    for (int idx = tid; idx < G3 * NF; idx += NTHREADS) {
        int c = idx / NF, f = idx % NF;
        s->wih_t[f * G3 + c] = Wih[idx];
    }
    for (int c = tid; c < 2 * HID; c += NTHREADS) s->brz[c] = bih[c] + bhh[c];
    for (int c = tid; c < HID; c += NTHREADS) {
        s->bin_[c] = bih[2 * HID + c];
        s->bhn[c]  = bhh[2 * HID + c];
    }
}

// One GRU step for this CTA's 64-row tile. Preconditions: x_t, h_t populated and
// visible (synced). Postcondition: h_t updated, all threads synced.
__device__ __forceinline__ void gru_step(Smem* s, int tx, int ty) {
    const int c0 = tx * 4;   // hidden-column group (0..60)
    const int r0 = ty * 4;   // batch-row group (0..60)

    float ar[4][4], az[4][4], ain[4][4], ahn[4][4];
    #pragma unroll
    for (int i = 0; i < 4; i++)
        #pragma unroll
        for (int j = 0; j < 4; j++) {
            ar[i][j]  = s->brz[c0 + j];
            az[i][j]  = s->brz[HID + c0 + j];
            ain[i][j] = s->bin_[c0 + j];
            ahn[i][j] = s->bhn[c0 + j];
        }

    // Input contribution (k over NF=8): r,z,and inn get x-part
    #pragma unroll
    for (int k = 0; k < NF; k++) {
        const float4 xv = *(const float4*)&s->x_t[k * ROWS + r0];
        const float4 wr = *(const float4*)&s->wih_t[k * G3 + c0];
        const float4 wz = *(const float4*)&s->wih_t[k * G3 + HID + c0];
        const float4 wn = *(const float4*)&s->wih_t[k * G3 + 2 * HID + c0];
        const float xa[4]  = {xv.x, xv.y, xv.z, xv.w};
        const float wra[4] = {wr.x, wr.y, wr.z, wr.w};
        const float wza[4] = {wz.x, wz.y, wz.z, wz.w};
        const float wna[4] = {wn.x, wn.y, wn.z, wn.w};
        #pragma unroll
        for (int i = 0; i < 4; i++)
            #pragma unroll
            for (int j = 0; j < 4; j++) {
                ar[i][j]  = fmaf(xa[i], wra[j], ar[i][j]);
                az[i][j]  = fmaf(xa[i], wza[j], az[i][j]);
                ain[i][j] = fmaf(xa[i], wna[j], ain[i][j]);
            }
    }

    // Hidden contribution (k over HID=64): r,z get h-part; hn accumulated separately
    #pragma unroll 4
    for (int k = 0; k < HID; k++) {
        const float4 hv = *(const float4*)&s->h_t[k * ROWS + r0];
        const float4 wr = *(const float4*)&s->whh_t[k * G3 + c0];
        const float4 wz = *(const float4*)&s->whh_t[k * G3 + HID + c0];
        const float4 wn = *(const float4*)&s->whh_t[k * G3 + 2 * HID + c0];
        const float ha[4]  = {hv.x, hv.y, hv.z, hv.w};
        const float wra[4] = {wr.x, wr.y, wr.z, wr.w};
        const float wza[4] = {wz.x, wz.y, wz.z, wz.w};
        const float wna[4] = {wn.x, wn.y, wn.z, wn.w};
        #pragma unroll
        for (int i = 0; i < 4; i++)
            #pragma unroll
            for (int j = 0; j < 4; j++) {
                ar[i][j]  = fmaf(ha[i], wra[j], ar[i][j]);
                az[i][j]  = fmaf(ha[i], wza[j], az[i][j]);
                ahn[i][j] = fmaf(ha[i], wna[j], ahn[i][j]);
            }
    }

    // Gates + state update. hnew[j][i] layout for the float4 transposed store.
    float hnew[4][4];
    #pragma unroll
    for (int j = 0; j < 4; j++) {
        const float4 ho = *(const float4*)&s->h_t[(c0 + j) * ROWS + r0];
        const float hoa[4] = {ho.x, ho.y, ho.z, ho.w};
        #pragma unroll
        for (int i = 0; i < 4; i++) {
            float r = sigf(ar[i][j]);
            float z = sigf(az[i][j]);
            float n = tanh_(fmaf(r, ahn[i][j], ain[i][j]));
            hnew[j][i] = fmaf(z, hoa[i] - n, n);   // (1-z)*n + z*h
        }
    }
    __syncthreads();   // all reads of old h_t complete
    #pragma unroll
    for (int j = 0; j < 4; j++) {
        float4 v = make_float4(hnew[j][0], hnew[j][1], hnew[j][2], hnew[j][3]);
        *(float4*)&s->h_t[(c0 + j) * ROWS + r0] = v;
    }
    __syncthreads();   // new h_t visible
}

extern __shared__ float smem_raw[];

__global__ void __launch_bounds__(NTHREADS)
seq2seq_gru_kernel(const float* __restrict__ x,  const float* __restrict__ xy,
                   const float* __restrict__ eWih, const float* __restrict__ eWhh,
                   const float* __restrict__ ebih, const float* __restrict__ ebhh,
                   const float* __restrict__ dWih, const float* __restrict__ dWhh,
                   const float* __restrict__ dbih, const float* __restrict__ dbhh,
                   const float* __restrict__ Wout, const float* __restrict__ bout,
                   float* __restrict__ out)
{
    Smem* s = (Smem*)smem_raw;
    const int tid = threadIdx.x;
    const int tx = tid % 16;
    const int ty = tid / 16;
    const int b0 = blockIdx.x * ROWS;

    // init h = 0
    for (int i = tid; i < HID * ROWS; i += NTHREADS) s->h_t[i] = 0.0f;

    load_phase_weights(s, eWih, eWhh, ebih, ebhh);

    // Wout [8,64] -> wout_t[k*8 + o]; bout
    for (int idx = tid; idx < HID * NO; idx += NTHREADS) {
        int o = idx / HID, k = idx % HID;
        s->wout_t[k * NO + o] = Wout[idx];
    }
    if (tid < NO) s->bout_s[tid] = bout[tid];
    __syncthreads();

    // ----- Encoder: 256 steps -----
    for (int t = 0; t < SEQ_LEN; t++) {
        if (tid < ROWS) {
            const float* xr = x + ((size_t)t * BATCH + b0 + tid) * NF;
            float4 a = *(const float4*)xr;
            float4 b = *(const float4*)(xr + 4);
            s->x_t[0 * ROWS + tid] = a.x;
            s->x_t[1 * ROWS + tid] = a.y;
            s->x_t[2 * ROWS + tid] = a.z;
            s->x_t[3 * ROWS + tid] = a.w;
            s->x_t[4 * ROWS + tid] = b.x;
            s->x_t[5 * ROWS + tid] = b.y;
            s->x_t[6 * ROWS + tid] = b.z;
            s->x_t[7 * ROWS + tid] = b.w;
        }
        __syncthreads();
        gru_step(s, tx, ty);
    }

    // ----- Switch to decoder weights; seed input with xy[0] -----
    load_phase_weights(s, dWih, dWhh, dbih, dbhh);
    if (tid < ROWS) {
        const float* xr = xy + ((size_t)b0 + tid) * NO;   // xy[0]
        float4 a = *(const float4*)xr;
        float4 b = *(const float4*)(xr + 4);
        s->x_t[0 * ROWS + tid] = a.x;
        s->x_t[1 * ROWS + tid] = a.y;
        s->x_t[2 * ROWS + tid] = a.z;
        s->x_t[3 * ROWS + tid] = a.w;
        s->x_t[4 * ROWS + tid] = b.x;
        s->x_t[5 * ROWS + tid] = b.y;
        s->x_t[6 * ROWS + tid] = b.z;
        s->x_t[7 * ROWS + tid] = b.w;
    }
    __syncthreads();

    // ----- Decoder: 128 steps, autoregressive through output projection -----
    for (int t = 0; t < LABEL_LEN; t++) {
        gru_step(s, tx, ty);   // consumes x_t, updates h_t (ends synced)

        // Output projection: 64 rows x 8 outs = 512 dots; 2 per thread.
        const int o    = tid & 7;
        const int row0 = tid >> 3;        // 0..31
        const int row1 = row0 + 32;
        float acc0 = 0.0f, acc1 = 0.0f;
        #pragma unroll 8
        for (int k = 0; k < HID; k++) {
            const float w = s->wout_t[k * NO + o];
            acc0 = fmaf(s->h_t[k * ROWS + row0], w, acc0);
            acc1 = fmaf(s->h_t[k * ROWS + row1], w, acc1);
        }
        acc0 += s->bout_s[o];
        acc1 += s->bout_s[o];

        float* op = out + ((size_t)t * BATCH + b0) * NO;
        op[row0 * NO + o] = acc0;
        op[row1 * NO + o] = acc1;

        // Feed back as next decoder input
        s->x_t[o * ROWS + row0] = acc0;
        s->x_t[o * ROWS + row1] = acc1;
        __syncthreads();
    }
}

extern "C" void kernel_launch(void* const* d_in, const int* in_sizes, int n_in,
                              void* d_out, int out_size) {
    const float* x    = (const float*)d_in[0];
    const float* xy   = (const float*)d_in[1];
    const float* eWih = (const float*)d_in[2];
    const float* eWhh = (const float*)d_in[3];
    const float* ebih = (const float*)d_in[4];
    const float* ebhh = (const float*)d_in[5];
    const float* dWih = (const float*)d_in[6];
    const float* dWhh = (const float*)d_in[7];
    const float* dbih = (const float*)d_in[8];
    const float* dbhh = (const float*)d_in[9];
    const float* Wout = (const float*)d_in[10];
    const float* bout = (const float*)d_in[11];
    float* out = (float*)d_out;

    const int smem_bytes = (int)sizeof(Smem);
    cudaFuncSetAttribute(seq2seq_gru_kernel,
                         cudaFuncAttributeMaxDynamicSharedMemorySize, smem_bytes);

    seq2seq_gru_kernel<<<NCTA, NTHREADS, smem_bytes>>>(
        x, xy, eWih, eWhh, ebih, ebhh, dWih, dWhh, dbih, dbhh, Wout, bout, out);
}